// round 5
// baseline (speedup 1.0000x reference)
#include <cuda_runtime.h>

#define S 1024
#define NB 4
#define PLANE (S * S)
#define TEXELS (NB * PLANE)   // 4M texels
#define EPS 1e-8f

// Fill tile geometry: out tile TW x TH; iter1 needs (TW+2)x(TH+2) = 32 cols
// (exactly one warp of lanes), input halo (TW+4)x(TH+4).
#define TW 30
#define TH 62
#define IW 34            // input ext width
#define IH 66            // input ext height
#define I1W 33           // iter1 buffer width (32 cols + 1 pad col)
#define I1H 64           // iter1 rows (TH+2)
#define GXT 35           // ceil(1024/30)
#define GYT 17           // ceil(1024/62)

// Scratch: 64 MB accumulator (rgb + weight).
__device__ float4 g_acc[TEXELS];

// Vectorized L2 reduction: one 16B atomic add instead of 4 scalar atomicAdds.
__device__ __forceinline__ void red_add_v4(float4* addr, float a, float b, float c, float d) {
    asm volatile("red.global.add.v4.f32 [%0], {%1, %2, %3, %4};"
                 :: "l"(addr), "f"(a), "f"(b), "f"(c), "f"(d)
                 : "memory");
}

// ---------------------------------------------------------------------------
// Bilinear splat: one thread per source pixel, 4 corner RED.v4 ops.
// _rn intrinsics: reference rounds mul/sub separately; FMA contraction of
// v = 1023 - y*1023 flips floor() for ~hundreds of pixels -> 1e-3 error.
// ---------------------------------------------------------------------------
__global__ void splat_kernel(const float* __restrict__ img,
                             const float2* __restrict__ uv) {
    int tid = blockIdx.x * blockDim.x + threadIdx.x;   // 0 .. 4M-1
    int n  = tid >> 20;
    int hw = tid & (PLANE - 1);

    float2 t = uv[tid];
    const float* base = img + (size_t)n * 3 * PLANE + hw;
    float r = __ldg(base);
    float g = __ldg(base + PLANE);
    float b = __ldg(base + 2 * PLANE);

    float u = __fmul_rn(t.x, 1023.0f);
    float v = __fsub_rn(1023.0f, __fmul_rn(t.y, 1023.0f));
    float x0f = floorf(u), y0f = floorf(v);
    float fx = __fsub_rn(u, x0f);
    float fy = __fsub_rn(v, y0f);
    int x0 = (int)x0f, y0 = (int)y0f;
    int x1 = x0 + 1,   y1 = y0 + 1;

    float gx = __fsub_rn(1.0f, fx);
    float gy = __fsub_rn(1.0f, fy);
    float w00 = __fmul_rn(gx, gy);
    float w10 = __fmul_rn(fx, gy);
    float w01 = __fmul_rn(gx, fy);
    float w11 = __fmul_rn(fx, fy);

    float4* accn = g_acc + n * PLANE;

    #define CORNER(XI, YI, WT) do {                                         \
        int xi = (XI), yi = (YI);                                           \
        float wt = (WT);                                                    \
        bool valid = ((unsigned)xi < (unsigned)S) &&                        \
                     ((unsigned)yi < (unsigned)S);                          \
        wt = valid ? wt : 0.f;                                              \
        int xc = min(max(xi, 0), S - 1);                                    \
        int yc = min(max(yi, 0), S - 1);                                    \
        red_add_v4(accn + yc * S + xc,                                      \
                   __fmul_rn(r, wt), __fmul_rn(g, wt),                      \
                   __fmul_rn(b, wt), wt);                                   \
    } while (0)

    CORNER(x0, y0, w00);
    CORNER(x1, y0, w10);
    CORNER(x0, y1, w01);
    CORNER(x1, y1, w11);
    #undef CORNER
}

// ---------------------------------------------------------------------------
// Fused normalize + 2 hole-fill iterations, rolling-register vertical window.
// Same stencil both iterations (stored p == tex*m, holes carry exact 0):
//   nsum = box3(p), ncnt = box3(m)
//   out = m ? p : (ncnt>0 ? nsum/ncnt : 0);  out_m = m | (ncnt>0)
// ---------------------------------------------------------------------------
__device__ __forceinline__ float4 add3(float4 a, float4 b, float4 c) {
    return make_float4(__fadd_rn(__fadd_rn(a.x, b.x), c.x),
                       __fadd_rn(__fadd_rn(a.y, b.y), c.y),
                       __fadd_rn(__fadd_rn(a.z, b.z), c.z),
                       __fadd_rn(__fadd_rn(a.w, b.w), c.w));
}

__device__ __forceinline__ float4 fin(float4 cen, float4 ns) {
    bool covered = cen.w > 0.f;
    float nm = ns.w > 0.f ? 1.f : 0.f;
    float nd = fmaxf(ns.w, EPS);
    float4 o;
    o.x = covered ? cen.x : __fmul_rn(__fdiv_rn(ns.x, nd), nm);
    o.y = covered ? cen.y : __fmul_rn(__fdiv_rn(ns.y, nd), nm);
    o.z = covered ? cen.z : __fmul_rn(__fdiv_rn(ns.z, nd), nm);
    o.w = fmaxf(cen.w, nm);
    return o;
}

// horizontal 3-sum of row `row` starting at column `c` (c, c+1, c+2)
__device__ __forceinline__ float4 hsum(const float4* buf, int stride, int row, int c) {
    const float4* p = buf + row * stride + c;
    return add3(p[0], p[1], p[2]);
}

extern __shared__ float4 s_dyn[];

__global__ __launch_bounds__(256) void fill2x_kernel(float* __restrict__ otex) {
    float4* s_in = s_dyn;              // [IH][IW]  normalized input + halo
    float4* s_i1 = s_dyn + IH * IW;    // [I1H][I1W] iter-1 result

    int n   = blockIdx.z;
    int tx0 = blockIdx.x * TW;
    int ty0 = blockIdx.y * TH;
    const float4* __restrict__ base = g_acc + n * PLANE;
    int t    = threadIdx.x;   // 256 threads = 8 warps
    int lane = t & 31;
    int wg   = t >> 5;

    // ---- Load IHxIW halo, normalize: tex = acc/max(w,eps); p = tex*m; m = w>0
    for (int i = t; i < IH * IW; i += 256) {
        int r = i / IW, c = i - r * IW;
        int gx = tx0 + c - 2, gy = ty0 + r - 2;
        float4 v = make_float4(0.f, 0.f, 0.f, 0.f);
        if ((unsigned)gx < (unsigned)S && (unsigned)gy < (unsigned)S) {
            v = __ldg(base + gy * S + gx);
            float m = v.w > 0.f ? 1.f : 0.f;
            float d = fmaxf(v.w, EPS);
            v.x = __fmul_rn(__fdiv_rn(v.x, d), m);
            v.y = __fmul_rn(__fdiv_rn(v.y, d), m);
            v.z = __fmul_rn(__fdiv_rn(v.z, d), m);
            v.w = m;
        }
        s_in[i] = v;
    }
    __syncthreads();

    // ---- Iter 1: lane covers column x = lane-1 (32 cols), warp wg covers
    //      8 rows y = wg*8-1 .. wg*8+6  (64 rows total = I1H).
    //      s_in index: (x,y) -> row y+2, col x+2; hsum cols x-1..x+1 -> lane..lane+2
    {
        int y0 = wg * 8 - 1;
        int gx = tx0 + lane - 1;
        bool xin = (unsigned)gx < (unsigned)S;
        float4 hm = hsum(s_in, IW, y0 + 1, lane);   // hsum(y0-1)
        float4 h0 = hsum(s_in, IW, y0 + 2, lane);   // hsum(y0)
        #pragma unroll
        for (int k = 0; k < 8; k++) {
            int y = y0 + k;
            float4 hp  = hsum(s_in, IW, y + 3, lane);   // hsum(y+1)
            float4 cen = s_in[(y + 2) * IW + lane + 1];
            float4 o = fin(cen, add3(hm, h0, hp));
            int gy = ty0 + y;
            if (!xin || (unsigned)gy >= (unsigned)S)
                o = make_float4(0.f, 0.f, 0.f, 0.f);    // reference zero-pads
            s_i1[(y + 1) * I1W + lane] = o;
            hm = h0; h0 = hp;
        }
    }
    __syncthreads();

    // ---- Iter 2: lane -> out col x = lane (valid lane < TW), rows y = wg*8..
    //      s_i1 col c holds x = c-1; hsum needs x-1..x+1 -> cols lane..lane+2
    if (lane < TW) {
        int y0 = wg * 8;
        float4 hm = hsum(s_i1, I1W, y0,     lane);  // hsum(y0-1)
        float4 h0 = hsum(s_i1, I1W, y0 + 1, lane);  // hsum(y0)
        #pragma unroll
        for (int k = 0; k < 8; k++) {
            int y = y0 + k;
            if (y >= TH) break;
            float4 hp  = hsum(s_i1, I1W, y + 2, lane);
            float4 cen = s_i1[(y + 1) * I1W + lane + 1];
            float4 o = fin(cen, add3(hm, h0, hp));

            int gy = ty0 + y, gx = tx0 + lane;
            if ((unsigned)gy < (unsigned)S && (unsigned)gx < (unsigned)S) {
                float* op = otex + ((size_t)n * PLANE + (size_t)gy * S + gx) * 3;
                op[0] = o.x; op[1] = o.y; op[2] = o.z;
            }
            hm = h0; h0 = hp;
        }
    }
}

// ---------------------------------------------------------------------------
// Launch: memset(acc) -> splat -> fused normalize+fill2x (-> d_out)
// ---------------------------------------------------------------------------
extern "C" void kernel_launch(void* const* d_in, const int* in_sizes, int n_in,
                              void* d_out, int out_size) {
    const float*  img = (const float*)d_in[0];      // [4,3,1024,1024]
    const float2* uv  = (const float2*)d_in[1];     // [4,1024,1024,2]
    float* out = (float*)d_out;                     // [4,1024,1024,3]

    void* acc_ptr = 0;
    cudaGetSymbolAddress(&acc_ptr, g_acc);
    cudaMemsetAsync(acc_ptr, 0, (size_t)TEXELS * sizeof(float4), 0);

    splat_kernel<<<TEXELS / 256, 256>>>(img, uv);

    const int smem_bytes = (IH * IW + I1H * I1W) * (int)sizeof(float4);  // 69,696
    cudaFuncSetAttribute(fill2x_kernel, cudaFuncAttributeMaxDynamicSharedMemorySize,
                         smem_bytes);
    dim3 grid(GXT, GYT, NB);
    fill2x_kernel<<<grid, 256, smem_bytes>>>(out);
}

// round 6
// speedup vs baseline: 1.0356x; 1.0356x over previous
#include <cuda_runtime.h>

#define S 1024
#define NB 4
#define PLANE (S * S)
#define TEXELS (NB * PLANE)   // 4M texels
#define EPS 1e-8f

// Scratch: 64 MB accumulator (rgb + weight).
__device__ float4 g_acc[TEXELS];

// Vectorized L2 reduction: one 16B atomic add instead of 4 scalar atomicAdds.
__device__ __forceinline__ void red_add_v4(float4* addr, float a, float b, float c, float d) {
    asm volatile("red.global.add.v4.f32 [%0], {%1, %2, %3, %4};"
                 :: "l"(addr), "f"(a), "f"(b), "f"(c), "f"(d)
                 : "memory");
}

// ---------------------------------------------------------------------------
// Bilinear splat, 2 horizontally-adjacent pixels per thread.
// One float4 UV load (2 pixels), three float2 img loads, 8 corner REDs.
// _rn intrinsics: reference rounds mul/sub separately; FMA contraction of
// v = 1023 - y*1023 flips floor() for ~hundreds of pixels -> 1e-3 error.
// ---------------------------------------------------------------------------
__device__ __forceinline__ void splat_one(float4* accn, float tx, float ty,
                                          float r, float g, float b) {
    float u = __fmul_rn(tx, 1023.0f);
    float v = __fsub_rn(1023.0f, __fmul_rn(ty, 1023.0f));
    float x0f = floorf(u), y0f = floorf(v);
    float fx = __fsub_rn(u, x0f);
    float fy = __fsub_rn(v, y0f);
    int x0 = (int)x0f, y0 = (int)y0f;
    int x1 = x0 + 1,   y1 = y0 + 1;

    float gx = __fsub_rn(1.0f, fx);
    float gy = __fsub_rn(1.0f, fy);
    float w00 = __fmul_rn(gx, gy);
    float w10 = __fmul_rn(fx, gy);
    float w01 = __fmul_rn(gx, fy);
    float w11 = __fmul_rn(fx, fy);

    #define CORNER(XI, YI, WT) do {                                         \
        int xi = (XI), yi = (YI);                                           \
        float wt = (WT);                                                    \
        bool valid = ((unsigned)xi < (unsigned)S) &&                        \
                     ((unsigned)yi < (unsigned)S);                          \
        wt = valid ? wt : 0.f;                                              \
        int xc = min(max(xi, 0), S - 1);                                    \
        int yc = min(max(yi, 0), S - 1);                                    \
        red_add_v4(accn + yc * S + xc,                                      \
                   __fmul_rn(r, wt), __fmul_rn(g, wt),                      \
                   __fmul_rn(b, wt), wt);                                   \
    } while (0)

    CORNER(x0, y0, w00);
    CORNER(x1, y0, w10);
    CORNER(x0, y1, w01);
    CORNER(x1, y1, w11);
    #undef CORNER
}

__global__ void splat_kernel(const float* __restrict__ img,
                             const float4* __restrict__ uv2) {
    int tid = blockIdx.x * blockDim.x + threadIdx.x;   // 0 .. 2M-1
    int p0 = tid << 1;                                 // even pixel index
    int n  = p0 >> 20;
    int hw = p0 & (PLANE - 1);

    float4 t = __ldg(uv2 + tid);                       // (u0,v0,u1,v1)
    const float* base = img + (size_t)n * 3 * PLANE + hw;
    float2 rr = *(const float2*)(base);
    float2 gg = *(const float2*)(base + PLANE);
    float2 bb = *(const float2*)(base + 2 * PLANE);

    float4* accn = g_acc + n * PLANE;
    splat_one(accn, t.x, t.y, rr.x, gg.x, bb.x);
    splat_one(accn, t.z, t.w, rr.y, gg.y, bb.y);
}

// ---------------------------------------------------------------------------
// Fused normalize + TWO hole-fill iterations (R4 structure: separable box,
// 40 KB static smem, 5 blocks/SM). Invariant: stored p == tex*m, holes are 0:
//   nsum = box3(p), ncnt = box3(m)
//   out = m ? p : (ncnt>0 ? nsum/ncnt : 0);  out_m = m | (ncnt>0)
// ---------------------------------------------------------------------------
__device__ __forceinline__ float4 add3(float4 a, float4 b, float4 c) {
    return make_float4(__fadd_rn(__fadd_rn(a.x, b.x), c.x),
                       __fadd_rn(__fadd_rn(a.y, b.y), c.y),
                       __fadd_rn(__fadd_rn(a.z, b.z), c.z),
                       __fadd_rn(__fadd_rn(a.w, b.w), c.w));
}

__device__ __forceinline__ float4 fin(float4 cen, float4 ns) {
    bool covered = cen.w > 0.f;
    float nm = ns.w > 0.f ? 1.f : 0.f;
    float nd = fmaxf(ns.w, EPS);
    float4 o;
    o.x = covered ? cen.x : __fmul_rn(__fdiv_rn(ns.x, nd), nm);
    o.y = covered ? cen.y : __fmul_rn(__fdiv_rn(ns.y, nd), nm);
    o.z = covered ? cen.z : __fmul_rn(__fdiv_rn(ns.z, nd), nm);
    o.w = fmaxf(cen.w, nm);
    return o;
}

__global__ __launch_bounds__(256) void fill2x_kernel(float* __restrict__ otex) {
    __shared__ float4 sm[36 * 36];   // normalized tile+halo; later iter-1 result (34x34, stride 36)
    __shared__ float4 hs[36 * 34];   // horizontal 3-sums (iter1); later iter2 (34x32, stride 32)

    int n   = blockIdx.z;
    int tx0 = blockIdx.x << 5;
    int ty0 = blockIdx.y << 5;
    const float4* __restrict__ base = g_acc + n * PLANE;
    int t = threadIdx.x;   // 256 threads

    // ---- Load 36x36 halo, normalize: tex = acc/max(w,eps); p = tex*m; m = w>0
    for (int i = t; i < 36 * 36; i += 256) {
        int ly = i / 36, lx = i - ly * 36;
        int gx = tx0 + lx - 2, gy = ty0 + ly - 2;
        float4 v = make_float4(0.f, 0.f, 0.f, 0.f);
        if ((unsigned)gx < (unsigned)S && (unsigned)gy < (unsigned)S) {
            v = __ldg(base + gy * S + gx);
            float m = v.w > 0.f ? 1.f : 0.f;
            float d = fmaxf(v.w, EPS);
            v.x = __fmul_rn(__fdiv_rn(v.x, d), m);
            v.y = __fmul_rn(__fdiv_rn(v.y, d), m);
            v.z = __fmul_rn(__fdiv_rn(v.z, d), m);
            v.w = m;
        }
        sm[i] = v;
    }
    __syncthreads();

    // ---- Iter 1 horizontal 3-sums: 36 rows x 34 cols
    for (int i = t; i < 36 * 34; i += 256) {
        int r = i / 34, c = i - r * 34;
        const float4* row = sm + r * 36 + c;
        hs[i] = add3(row[0], row[1], row[2]);
    }
    __syncthreads();

    // ---- Iter 1 vertical + finalize into registers (34x34 outputs)
    float4 reg[5];
    int cnt = 0;
    for (int i = t; i < 34 * 34; i += 256) {
        int a = i / 34, b = i - a * 34;
        float4 ns  = add3(hs[a * 34 + b], hs[(a + 1) * 34 + b], hs[(a + 2) * 34 + b]);
        float4 cen = sm[(a + 1) * 36 + (b + 1)];
        float4 o = fin(cen, ns);
        // zero outside the image: reference pads with exact zeros
        int gy = ty0 + a - 1, gx = tx0 + b - 1;
        if ((unsigned)gx >= (unsigned)S || (unsigned)gy >= (unsigned)S)
            o = make_float4(0.f, 0.f, 0.f, 0.f);
        reg[cnt++] = o;
    }
    __syncthreads();

    // ---- Write iter-1 result back over sm (top-left 34x34, keep stride 36)
    cnt = 0;
    for (int i = t; i < 34 * 34; i += 256) {
        int a = i / 34, b = i - a * 34;
        sm[a * 36 + b] = reg[cnt++];
    }
    __syncthreads();

    // ---- Iter 2 horizontal 3-sums: 34 rows x 32 cols (reuse hs, stride 32)
    for (int i = t; i < 34 * 32; i += 256) {
        int r = i >> 5, c = i & 31;
        const float4* row = sm + r * 36 + c;
        hs[r * 32 + c] = add3(row[0], row[1], row[2]);
    }
    __syncthreads();

    // ---- Iter 2 vertical + finalize -> packed [N,S,S,3] output
    int lx = t & 31;
    for (int ly = t >> 5; ly < 32; ly += 8) {
        float4 ns  = add3(hs[ly * 32 + lx], hs[(ly + 1) * 32 + lx], hs[(ly + 2) * 32 + lx]);
        float4 cen = sm[(ly + 1) * 36 + (lx + 1)];
        float4 o = fin(cen, ns);

        int gy = ty0 + ly, gx = tx0 + lx;
        float* op = otex + ((size_t)n * PLANE + (size_t)gy * S + gx) * 3;
        op[0] = o.x; op[1] = o.y; op[2] = o.z;
    }
}

// ---------------------------------------------------------------------------
// Launch: memset(acc) -> splat (2 px/thread) -> fused normalize+fill2x
// ---------------------------------------------------------------------------
extern "C" void kernel_launch(void* const* d_in, const int* in_sizes, int n_in,
                              void* d_out, int out_size) {
    const float*  img = (const float*)d_in[0];      // [4,3,1024,1024]
    const float4* uv2 = (const float4*)d_in[1];     // [4,1024,1024,2] as pairs
    float* out = (float*)d_out;                     // [4,1024,1024,3]

    void* acc_ptr = 0;
    cudaGetSymbolAddress(&acc_ptr, g_acc);
    cudaMemsetAsync(acc_ptr, 0, (size_t)TEXELS * sizeof(float4), 0);

    splat_kernel<<<(TEXELS / 2) / 256, 256>>>(img, uv2);

    dim3 grid(S / 32, S / 32, NB);
    fill2x_kernel<<<grid, 256>>>(out);
}

// round 7
// speedup vs baseline: 1.0945x; 1.0569x over previous
#include <cuda_runtime.h>

#define S 1024
#define NB 4
#define PLANE (S * S)
#define TEXELS (NB * PLANE)   // 4M texels
#define EPS 1e-8f

// Scratch: 64 MB accumulator (rgb + weight).
__device__ float4 g_acc[TEXELS];

// Vectorized L2 reduction: one 16B atomic add instead of 4 scalar atomicAdds.
__device__ __forceinline__ void red_add_v4(float4* addr, float a, float b, float c, float d) {
    asm volatile("red.global.add.v4.f32 [%0], {%1, %2, %3, %4};"
                 :: "l"(addr), "f"(a), "f"(b), "f"(c), "f"(d)
                 : "memory");
}

// ---------------------------------------------------------------------------
// Bilinear splat, 2 horizontally-adjacent pixels per thread.
// _rn intrinsics here are LOAD-BEARING: reference rounds mul/sub separately;
// FMA contraction of v = 1023 - y*1023 flips floor() for ~hundreds of pixels
// -> O(1) errors -> 1e-3 rel_err. Do not relax.
// ---------------------------------------------------------------------------
__device__ __forceinline__ void splat_one(float4* accn, float tx, float ty,
                                          float r, float g, float b) {
    float u = __fmul_rn(tx, 1023.0f);
    float v = __fsub_rn(1023.0f, __fmul_rn(ty, 1023.0f));
    float x0f = floorf(u), y0f = floorf(v);
    float fx = __fsub_rn(u, x0f);
    float fy = __fsub_rn(v, y0f);
    int x0 = (int)x0f, y0 = (int)y0f;
    int x1 = x0 + 1,   y1 = y0 + 1;

    float gx = __fsub_rn(1.0f, fx);
    float gy = __fsub_rn(1.0f, fy);
    float w00 = __fmul_rn(gx, gy);
    float w10 = __fmul_rn(fx, gy);
    float w01 = __fmul_rn(gx, fy);
    float w11 = __fmul_rn(fx, fy);

    #define CORNER(XI, YI, WT) do {                                         \
        int xi = (XI), yi = (YI);                                           \
        float wt = (WT);                                                    \
        bool valid = ((unsigned)xi < (unsigned)S) &&                        \
                     ((unsigned)yi < (unsigned)S);                          \
        wt = valid ? wt : 0.f;                                              \
        int xc = min(max(xi, 0), S - 1);                                    \
        int yc = min(max(yi, 0), S - 1);                                    \
        red_add_v4(accn + yc * S + xc,                                      \
                   __fmul_rn(r, wt), __fmul_rn(g, wt),                      \
                   __fmul_rn(b, wt), wt);                                   \
    } while (0)

    CORNER(x0, y0, w00);
    CORNER(x1, y0, w10);
    CORNER(x0, y1, w01);
    CORNER(x1, y1, w11);
    #undef CORNER
}

__global__ void splat_kernel(const float* __restrict__ img,
                             const float4* __restrict__ uv2) {
    int tid = blockIdx.x * blockDim.x + threadIdx.x;   // 0 .. 2M-1
    int p0 = tid << 1;                                 // even pixel index
    int n  = p0 >> 20;
    int hw = p0 & (PLANE - 1);

    float4 t = __ldg(uv2 + tid);                       // (u0,v0,u1,v1)
    const float* base = img + (size_t)n * 3 * PLANE + hw;
    float2 rr = *(const float2*)(base);
    float2 gg = *(const float2*)(base + PLANE);
    float2 bb = *(const float2*)(base + 2 * PLANE);

    float4* accn = g_acc + n * PLANE;
    splat_one(accn, t.x, t.y, rr.x, gg.x, bb.x);
    splat_one(accn, t.z, t.w, rr.y, gg.y, bb.y);
}

// ---------------------------------------------------------------------------
// Fused normalize + TWO hole-fill iterations (separable box, 40 KB smem).
// Invariant: stored p == tex*m, holes carry 0, so both iterations are:
//   nsum = box3(p), ncnt = box3(m)
//   out = m ? p : (ncnt>0 ? nsum/ncnt : 0);  out_m = m | (ncnt>0)
// Divisions use reciprocal-multiply (MUFU.RCP, ~2 ulp): rel_err budget is
// 1e-3 and we sit at ~1e-7; the kernel is issue-bound so the ~12-instr IEEE
// div slow paths (9 per texel) were pure overhead.
// ---------------------------------------------------------------------------
__device__ __forceinline__ float4 add3(float4 a, float4 b, float4 c) {
    return make_float4(__fadd_rn(__fadd_rn(a.x, b.x), c.x),
                       __fadd_rn(__fadd_rn(a.y, b.y), c.y),
                       __fadd_rn(__fadd_rn(a.z, b.z), c.z),
                       __fadd_rn(__fadd_rn(a.w, b.w), c.w));
}

__device__ __forceinline__ float4 fin(float4 cen, float4 ns) {
    bool covered = cen.w > 0.f;
    float nm  = ns.w > 0.f ? 1.f : 0.f;
    float inv = nm * __frcp_rn(fmaxf(ns.w, EPS));   // 0 when hole has no neighbors
    float4 o;
    o.x = covered ? cen.x : ns.x * inv;
    o.y = covered ? cen.y : ns.y * inv;
    o.z = covered ? cen.z : ns.z * inv;
    o.w = fmaxf(cen.w, nm);
    return o;
}

__global__ __launch_bounds__(256) void fill2x_kernel(float* __restrict__ otex) {
    __shared__ float4 sm[36 * 36];   // normalized tile+halo; later iter-1 result (34x34, stride 36)
    __shared__ float4 hs[36 * 34];   // horizontal 3-sums (iter1); later iter2 (34x32, stride 32)

    int n   = blockIdx.z;
    int tx0 = blockIdx.x << 5;
    int ty0 = blockIdx.y << 5;
    const float4* __restrict__ base = g_acc + n * PLANE;
    int t = threadIdx.x;   // 256 threads

    // ---- Load 36x36 halo, normalize: tex = acc/max(w,eps); p = tex*m; m = w>0
    for (int i = t; i < 36 * 36; i += 256) {
        int ly = i / 36, lx = i - ly * 36;
        int gx = tx0 + lx - 2, gy = ty0 + ly - 2;
        float4 v = make_float4(0.f, 0.f, 0.f, 0.f);
        if ((unsigned)gx < (unsigned)S && (unsigned)gy < (unsigned)S) {
            v = __ldg(base + gy * S + gx);
            float m  = v.w > 0.f ? 1.f : 0.f;
            float sc = m * __frcp_rn(fmaxf(v.w, EPS));
            v.x *= sc; v.y *= sc; v.z *= sc;
            v.w = m;
        }
        sm[i] = v;
    }
    __syncthreads();

    // ---- Iter 1 horizontal 3-sums: 36 rows x 34 cols
    for (int i = t; i < 36 * 34; i += 256) {
        int r = i / 34, c = i - r * 34;
        const float4* row = sm + r * 36 + c;
        hs[i] = add3(row[0], row[1], row[2]);
    }
    __syncthreads();

    // ---- Iter 1 vertical + finalize into registers (34x34 outputs)
    float4 reg[5];
    int cnt = 0;
    for (int i = t; i < 34 * 34; i += 256) {
        int a = i / 34, b = i - a * 34;
        float4 ns  = add3(hs[a * 34 + b], hs[(a + 1) * 34 + b], hs[(a + 2) * 34 + b]);
        float4 cen = sm[(a + 1) * 36 + (b + 1)];
        float4 o = fin(cen, ns);
        // zero outside the image: reference pads with exact zeros
        int gy = ty0 + a - 1, gx = tx0 + b - 1;
        if ((unsigned)gx >= (unsigned)S || (unsigned)gy >= (unsigned)S)
            o = make_float4(0.f, 0.f, 0.f, 0.f);
        reg[cnt++] = o;
    }
    __syncthreads();

    // ---- Write iter-1 result back over sm (top-left 34x34, keep stride 36)
    cnt = 0;
    for (int i = t; i < 34 * 34; i += 256) {
        int a = i / 34, b = i - a * 34;
        sm[a * 36 + b] = reg[cnt++];
    }
    __syncthreads();

    // ---- Iter 2 horizontal 3-sums: 34 rows x 32 cols (reuse hs, stride 32)
    for (int i = t; i < 34 * 32; i += 256) {
        int r = i >> 5, c = i & 31;
        const float4* row = sm + r * 36 + c;
        hs[r * 32 + c] = add3(row[0], row[1], row[2]);
    }
    __syncthreads();

    // ---- Iter 2 vertical + finalize -> packed [N,S,S,3] output
    int lx = t & 31;
    for (int ly = t >> 5; ly < 32; ly += 8) {
        float4 ns  = add3(hs[ly * 32 + lx], hs[(ly + 1) * 32 + lx], hs[(ly + 2) * 32 + lx]);
        float4 cen = sm[(ly + 1) * 36 + (lx + 1)];
        float4 o = fin(cen, ns);

        int gy = ty0 + ly, gx = tx0 + lx;
        float* op = otex + ((size_t)n * PLANE + (size_t)gy * S + gx) * 3;
        op[0] = o.x; op[1] = o.y; op[2] = o.z;
    }
}

// ---------------------------------------------------------------------------
// Launch: memset(acc) -> splat (2 px/thread) -> fused normalize+fill2x
// ---------------------------------------------------------------------------
extern "C" void kernel_launch(void* const* d_in, const int* in_sizes, int n_in,
                              void* d_out, int out_size) {
    const float*  img = (const float*)d_in[0];      // [4,3,1024,1024]
    const float4* uv2 = (const float4*)d_in[1];     // [4,1024,1024,2] as pairs
    float* out = (float*)d_out;                     // [4,1024,1024,3]

    void* acc_ptr = 0;
    cudaGetSymbolAddress(&acc_ptr, g_acc);
    cudaMemsetAsync(acc_ptr, 0, (size_t)TEXELS * sizeof(float4), 0);

    splat_kernel<<<(TEXELS / 2) / 256, 256>>>(img, uv2);

    dim3 grid(S / 32, S / 32, NB);
    fill2x_kernel<<<grid, 256>>>(out);
}

// round 9
// speedup vs baseline: 1.1856x; 1.0832x over previous
#include <cuda_runtime.h>

#define S 1024
#define NB 4
#define PLANE (S * S)
#define TEXELS (NB * PLANE)   // 4M texels
#define EPS 1e-8f

// Fill tile geometry: 30x30 outputs; iter1 = 32x32 (exactly one warp of
// lanes wide); input halo 34x34. smem = 35.4 KB -> 5 blocks/SM.
#define TW 30
#define IW 34
#define I1W 33           // iter1 stride (32 cols + 1 pad)
#define GT 35            // ceil(1024/30)

// Scratch: 64 MB accumulator (rgb + weight).
__device__ float4 g_acc[TEXELS];

// Vectorized L2 reduction: one 16B atomic add instead of 4 scalar atomicAdds.
__device__ __forceinline__ void red_add_v4(float4* addr, float a, float b, float c, float d) {
    asm volatile("red.global.add.v4.f32 [%0], {%1, %2, %3, %4};"
                 :: "l"(addr), "f"(a), "f"(b), "f"(c), "f"(d)
                 : "memory");
}

// ---------------------------------------------------------------------------
// Bilinear splat, 2 horizontally-adjacent pixels per thread.
// _rn intrinsics here are LOAD-BEARING: reference rounds mul/sub separately;
// FMA contraction of v = 1023 - y*1023 flips floor() for ~hundreds of pixels
// -> O(1) errors -> 1e-3 rel_err. Do not relax.
// ---------------------------------------------------------------------------
__device__ __forceinline__ void splat_one(float4* accn, float tx, float ty,
                                          float r, float g, float b) {
    float u = __fmul_rn(tx, 1023.0f);
    float v = __fsub_rn(1023.0f, __fmul_rn(ty, 1023.0f));
    float x0f = floorf(u), y0f = floorf(v);
    float fx = __fsub_rn(u, x0f);
    float fy = __fsub_rn(v, y0f);
    int x0 = (int)x0f, y0 = (int)y0f;
    int x1 = x0 + 1,   y1 = y0 + 1;

    float gx = __fsub_rn(1.0f, fx);
    float gy = __fsub_rn(1.0f, fy);
    float w00 = __fmul_rn(gx, gy);
    float w10 = __fmul_rn(fx, gy);
    float w01 = __fmul_rn(gx, fy);
    float w11 = __fmul_rn(fx, fy);

    #define CORNER(XI, YI, WT) do {                                         \
        int xi = (XI), yi = (YI);                                           \
        float wt = (WT);                                                    \
        bool valid = ((unsigned)xi < (unsigned)S) &&                        \
                     ((unsigned)yi < (unsigned)S);                          \
        wt = valid ? wt : 0.f;                                              \
        int xc = min(max(xi, 0), S - 1);                                    \
        int yc = min(max(yi, 0), S - 1);                                    \
        red_add_v4(accn + yc * S + xc,                                      \
                   __fmul_rn(r, wt), __fmul_rn(g, wt),                      \
                   __fmul_rn(b, wt), wt);                                   \
    } while (0)

    CORNER(x0, y0, w00);
    CORNER(x1, y0, w10);
    CORNER(x0, y1, w01);
    CORNER(x1, y1, w11);
    #undef CORNER
}

__global__ void splat_kernel(const float* __restrict__ img,
                             const float4* __restrict__ uv2) {
    int tid = blockIdx.x * blockDim.x + threadIdx.x;   // 0 .. 2M-1
    int p0 = tid << 1;                                 // even pixel index
    int n  = p0 >> 20;
    int hw = p0 & (PLANE - 1);

    float4 t = __ldg(uv2 + tid);                       // (u0,v0,u1,v1)
    const float* base = img + (size_t)n * 3 * PLANE + hw;
    float2 rr = *(const float2*)(base);
    float2 gg = *(const float2*)(base + PLANE);
    float2 bb = *(const float2*)(base + 2 * PLANE);

    float4* accn = g_acc + n * PLANE;
    splat_one(accn, t.x, t.y, rr.x, gg.x, bb.x);
    splat_one(accn, t.z, t.w, rr.y, gg.y, bb.y);
}

// ---------------------------------------------------------------------------
// Fused normalize + 2 hole-fill iterations, rolling-register vertical window.
// Invariant: stored p == tex*m, holes carry 0, so both iterations are:
//   nsum = box3(p), ncnt = box3(m)
//   out = m ? p : (ncnt>0 ? nsum/ncnt : 0);  out_m = m | (ncnt>0)
// Divisions are reciprocal-multiply (MUFU.RCP): rel_err budget 1e-3, we sit
// at ~5e-8. Arithmetic grouping identical to the verified R7 kernel.
// ---------------------------------------------------------------------------
__device__ __forceinline__ float4 add3(float4 a, float4 b, float4 c) {
    return make_float4(__fadd_rn(__fadd_rn(a.x, b.x), c.x),
                       __fadd_rn(__fadd_rn(a.y, b.y), c.y),
                       __fadd_rn(__fadd_rn(a.z, b.z), c.z),
                       __fadd_rn(__fadd_rn(a.w, b.w), c.w));
}

__device__ __forceinline__ float4 fin(float4 cen, float4 ns) {
    bool covered = cen.w > 0.f;
    float nm  = ns.w > 0.f ? 1.f : 0.f;
    float inv = nm * __frcp_rn(fmaxf(ns.w, EPS));   // 0 when hole has no neighbors
    float4 o;
    o.x = covered ? cen.x : ns.x * inv;
    o.y = covered ? cen.y : ns.y * inv;
    o.z = covered ? cen.z : ns.z * inv;
    o.w = fmaxf(cen.w, nm);
    return o;
}

// horizontal 3-sum starting at column c of row `row`
__device__ __forceinline__ float4 hsum(const float4* buf, int stride, int row, int c) {
    const float4* p = buf + row * stride + c;
    return add3(p[0], p[1], p[2]);
}

__global__ __launch_bounds__(256, 5) void fill2x_kernel(float* __restrict__ otex) {
    __shared__ float4 s_in[IW * IW];     // 34x34 normalized input + halo
    __shared__ float4 s_i1[32 * I1W];    // 32 rows x stride 33: iter-1 result

    int n   = blockIdx.z;
    int tx0 = blockIdx.x * TW;
    int ty0 = blockIdx.y * TW;
    const float4* __restrict__ base = g_acc + n * PLANE;
    int t    = threadIdx.x;   // 256 threads = 8 warps
    int lane = t & 31;
    int wg   = t >> 5;

    // ---- Load 34x34 halo, normalize: tex = acc/max(w,eps); p = tex*m; m = w>0
    for (int i = t; i < IW * IW; i += 256) {
        int r = i / IW, c = i - r * IW;
        int gx = tx0 + c - 2, gy = ty0 + r - 2;
        float4 v = make_float4(0.f, 0.f, 0.f, 0.f);
        if ((unsigned)gx < (unsigned)S && (unsigned)gy < (unsigned)S) {
            v = __ldg(base + gy * S + gx);
            float m  = v.w > 0.f ? 1.f : 0.f;
            float sc = m * __frcp_rn(fmaxf(v.w, EPS));
            v.x *= sc; v.y *= sc; v.z *= sc;
            v.w = m;
        }
        s_in[i] = v;
    }
    __syncthreads();

    // ---- Iter 1: lane -> col x = lane-1 (32 cols), warp wg -> 4 rows
    //      y = wg*4-1 .. wg*4+2. s_in(x,y) at row y+2, col x+2;
    //      hsum over cols x-1..x+1 -> lane..lane+2. Rolling hm/h0/hp.
    {
        int y0 = wg * 4 - 1;
        int gx = tx0 + lane - 1;
        bool xin = (unsigned)gx < (unsigned)S;
        float4 hm = hsum(s_in, IW, y0 + 1, lane);   // hsum(y0-1)
        float4 h0 = hsum(s_in, IW, y0 + 2, lane);   // hsum(y0)
        #pragma unroll
        for (int k = 0; k < 4; k++) {
            int y = y0 + k;
            float4 hp  = hsum(s_in, IW, y + 3, lane);   // hsum(y+1)
            float4 cen = s_in[(y + 2) * IW + lane + 1];
            float4 o = fin(cen, add3(hm, h0, hp));
            int gy = ty0 + y;
            if (!xin || (unsigned)gy >= (unsigned)S)
                o = make_float4(0.f, 0.f, 0.f, 0.f);    // reference zero-pads
            s_i1[(y + 1) * I1W + lane] = o;
            hm = h0; h0 = hp;
        }
    }
    __syncthreads();

    // ---- Iter 2: lane -> out col x = lane (lane < TW), warp wg -> rows
    //      y = wg*4 .. wg*4+3 (skip y >= TW). s_i1 col c holds x = c-1;
    //      hsum cols lane..lane+2 covers x-1..x+1; cen at col lane+1.
    if (lane < TW) {
        int y0 = wg * 4;
        float4 hm = hsum(s_i1, I1W, y0,     lane);  // hsum(y0-1)
        float4 h0 = hsum(s_i1, I1W, y0 + 1, lane);  // hsum(y0)
        #pragma unroll
        for (int k = 0; k < 4; k++) {
            int y = y0 + k;
            if (y >= TW) break;
            float4 hp  = hsum(s_i1, I1W, y + 2, lane);
            float4 cen = s_i1[(y + 1) * I1W + lane + 1];
            float4 o = fin(cen, add3(hm, h0, hp));

            int gy = ty0 + y, gx = tx0 + lane;
            if ((unsigned)gy < (unsigned)S && (unsigned)gx < (unsigned)S) {
                float* op = otex + ((size_t)n * PLANE + (size_t)gy * S + gx) * 3;
                op[0] = o.x; op[1] = o.y; op[2] = o.z;
            }
            hm = h0; h0 = hp;
        }
    }
}

// ---------------------------------------------------------------------------
// Launch: memset(acc) -> splat (2 px/thread) -> fused normalize+fill2x
// ---------------------------------------------------------------------------
extern "C" void kernel_launch(void* const* d_in, const int* in_sizes, int n_in,
                              void* d_out, int out_size) {
    const float*  img = (const float*)d_in[0];      // [4,3,1024,1024]
    const float4* uv2 = (const float4*)d_in[1];     // [4,1024,1024,2] as pairs
    float* out = (float*)d_out;                     // [4,1024,1024,3]

    void* acc_ptr = 0;
    cudaGetSymbolAddress(&acc_ptr, g_acc);
    cudaMemsetAsync(acc_ptr, 0, (size_t)TEXELS * sizeof(float4), 0);

    splat_kernel<<<(TEXELS / 2) / 256, 256>>>(img, uv2);

    dim3 grid(GT, GT, NB);
    fill2x_kernel<<<grid, 256>>>(out);
}